// round 7
// baseline (speedup 1.0000x reference)
#include <cuda_runtime.h>
#include <cuda_bf16.h>
#include <cstdint>

// ---------------------------------------------------------------------------
// Problem: B=16, S=4096, IN=N=OUT=256
//   Bu = u @ B_w^T + B_b                      (GEMM 65536x256x256)
//   s_t = relu(LN(s_{t-1} @ A^T + Bu_t))      (sequential scan, 16 lanes)
//   out = states @ C_w^T + C_b                (GEMM 65536x256x256)
// d_out = [states (16*4096*256) | outputs (16*4096*256)] fp32
// ---------------------------------------------------------------------------

#define BB 16
#define SS 4096
#define NN 256
static const size_t STATES_ELEMS = (size_t)BB * SS * NN;

// scratch for Bu (64 MB) — static device array (no allocation)
__device__ float g_Bu[(size_t)BB * SS * NN];

// ---------------------------------------------------------------------------
// helpers
// ---------------------------------------------------------------------------
__device__ __forceinline__ uint32_t smem_u32(const void* p) {
    uint32_t a;
    asm("{ .reg .u64 t; cvta.to.shared.u64 t, %1; cvt.u32.u64 %0, t; }"
        : "=r"(a) : "l"(p));
    return a;
}
__device__ __forceinline__ uint32_t mapa_u32(uint32_t a, uint32_t rank) {
    uint32_t r;
    asm("mapa.shared::cluster.u32 %0, %1, %2;" : "=r"(r) : "r"(a), "r"(rank));
    return r;
}
__device__ __forceinline__ void mbar_init(uint32_t mbar, uint32_t count) {
    asm volatile("mbarrier.init.shared.b64 [%0], %1;" :: "r"(mbar), "r"(count) : "memory");
}
__device__ __forceinline__ void arrive_expect_tx(uint32_t mbar, uint32_t tx) {
    asm volatile("mbarrier.arrive.expect_tx.shared.b64 _, [%0], %1;"
                 :: "r"(mbar), "r"(tx) : "memory");
}
// bulk copy local smem -> remote CTA smem, completing on the remote mbarrier
__device__ __forceinline__ void bulk_copy_cluster(uint32_t dst_cluster, uint32_t src_cta,
                                                  uint32_t bytes, uint32_t remote_mbar) {
    asm volatile("cp.async.bulk.shared::cluster.shared::cta.mbarrier::complete_tx::bytes "
                 "[%0], [%1], %2, [%3];"
                 :: "r"(dst_cluster), "r"(src_cta), "r"(bytes), "r"(remote_mbar) : "memory");
}
__device__ __forceinline__ void fence_proxy_async_cta() {
    asm volatile("fence.proxy.async.shared::cta;" ::: "memory");
}
// CTA-scope acquire wait: async-proxy complete_tx already makes the delivered
// data CTA-visible at the barrier; cluster-scope acquire (UCGABAR, ~490cyc) is
// NOT needed and was the round-3/5 tax.
__device__ __forceinline__ void wait_parity_cta(uint32_t mbar, uint32_t ph) {
    asm volatile(
        "{\n\t"
        ".reg .pred P;\n\t"
        "WL_%=:\n\t"
        "mbarrier.try_wait.parity.acquire.cta.shared::cta.b64 P, [%0], %1, 0x989680;\n\t"
        "@P bra.uni WD_%=;\n\t"
        "bra.uni WL_%=;\n\t"
        "WD_%=:\n\t"
        "}"
        :: "r"(mbar), "r"(ph) : "memory");
}
__device__ __forceinline__ void cluster_sync_() {
    asm volatile("barrier.cluster.arrive.aligned;" ::: "memory");
    asm volatile("barrier.cluster.wait.aligned;" ::: "memory");
}

// ---------------------------------------------------------------------------
// GEMM (NT):  C[m,n] = sum_k A[m,k] * W[n,k] + bias[n]
// M = 65536, N = 256, K = 256.  Tile 128x128, BK=8, 256 thr, 8x8 per thread.
// (round-3 version: 220us, regs=111 — the register-prefetch variant regressed)
// ---------------------------------------------------------------------------
__global__ __launch_bounds__(256)
void gemm_nt_kernel(const float* __restrict__ Amat,
                    const float* __restrict__ Wmat,
                    const float* __restrict__ bias,
                    float* __restrict__ C)
{
    __shared__ float As[8][128];
    __shared__ float Ws[8][128];

    const int tid = threadIdx.x;
    const int bm = blockIdx.x;
    const int bn = blockIdx.y;

    const int lrow = tid >> 1;          // 0..127
    const int kq   = (tid & 1) * 4;     // 0 or 4

    const float* ga = Amat + ((size_t)(bm * 128 + lrow)) * 256 + kq;
    const float* gw = Wmat + ((size_t)(bn * 128 + lrow)) * 256 + kq;

    const int ty = tid >> 4;            // 0..15 -> rows ty*8..+8
    const int tx = tid & 15;            // 0..15 -> cols tx*8..+8

    float acc[8][8];
    #pragma unroll
    for (int i = 0; i < 8; i++)
        #pragma unroll
        for (int j = 0; j < 8; j++) acc[i][j] = 0.f;

    for (int kt = 0; kt < 256; kt += 8) {
        float4 va = *(const float4*)(ga + kt);
        float4 vw = *(const float4*)(gw + kt);
        __syncthreads();
        As[kq + 0][lrow] = va.x; As[kq + 1][lrow] = va.y;
        As[kq + 2][lrow] = va.z; As[kq + 3][lrow] = va.w;
        Ws[kq + 0][lrow] = vw.x; Ws[kq + 1][lrow] = vw.y;
        Ws[kq + 2][lrow] = vw.z; Ws[kq + 3][lrow] = vw.w;
        __syncthreads();

        #pragma unroll
        for (int k = 0; k < 8; k++) {
            float4 a0 = *(const float4*)&As[k][ty * 8];
            float4 a1 = *(const float4*)&As[k][ty * 8 + 4];
            float4 b0 = *(const float4*)&Ws[k][tx * 8];
            float4 b1 = *(const float4*)&Ws[k][tx * 8 + 4];
            float ar[8] = {a0.x, a0.y, a0.z, a0.w, a1.x, a1.y, a1.z, a1.w};
            float br[8] = {b0.x, b0.y, b0.z, b0.w, b1.x, b1.y, b1.z, b1.w};
            #pragma unroll
            for (int i = 0; i < 8; i++)
                #pragma unroll
                for (int j = 0; j < 8; j++)
                    acc[i][j] += ar[i] * br[j];
        }
    }

    float bs[8];
    #pragma unroll
    for (int j = 0; j < 8; j++) bs[j] = bias[bn * 128 + tx * 8 + j];

    #pragma unroll
    for (int i = 0; i < 8; i++) {
        size_t m = (size_t)bm * 128 + ty * 8 + i;
        float4 o0, o1;
        o0.x = acc[i][0] + bs[0]; o0.y = acc[i][1] + bs[1];
        o0.z = acc[i][2] + bs[2]; o0.w = acc[i][3] + bs[3];
        o1.x = acc[i][4] + bs[4]; o1.y = acc[i][5] + bs[5];
        o1.z = acc[i][6] + bs[6]; o1.w = acc[i][7] + bs[7];
        float* cp = C + m * 256 + bn * 128 + tx * 8;
        *(float4*)(cp)     = o0;
        *(float4*)(cp + 4) = o1;
    }
}

// ---------------------------------------------------------------------------
// Scan kernel: 16 clusters of 8 CTAs (one cluster per batch lane).
// CTA rank r holds A rows [32r, 32r+32) in REGISTERS (32 regs/thread).
// Per step:
//   register GEMV -> 8-lane shfl reduce
//   -> lane colg==0 stages its row value (stage[p]) AND writes it into the
//      local raw[p] slice (self needs no transit)
//   -> __syncthreads -> threads 0..6: fence.proxy.async + ONE 128B bulk copy
//      each to a distinct peer CTA's raw[p] slice, completing on the peer's
//      tx-counting mbarrier (expect 7*128B per phase -> only 7 tx updates)
//   -> warp 0 alone waits (CTA-scope acquire, fast TRYWAIT path), thread 0
//      re-arms for t+2, __syncthreads releases the CTA
//   -> redundant per-warp LN stats + normalize + relu -> next step.
// ---------------------------------------------------------------------------
#define SPAD(i) ((i) + ((i) >> 5) * 4)   // pad 16B per 32 floats
#define TX_BYTES 896u                    // 7 peers * 128 B per phase

__global__ __launch_bounds__(256)
__cluster_dims__(8, 1, 1)
void scan_kernel(const float* __restrict__ A,
                 const float* __restrict__ ln_g,
                 const float* __restrict__ ln_b,
                 float* __restrict__ states)
{
    __shared__ __align__(16) float s_pad[256 + 32];
    __shared__ __align__(16) float raw[2][256];     // incoming, by step parity
    __shared__ __align__(16) float stage[2][32];    // outgoing, by step parity
    __shared__ __align__(8)  unsigned long long bars[2];

    const int tid  = threadIdx.x;
    const int lane = tid & 31;
    const int wid  = tid >> 5;

    uint32_t rank;
    asm("mov.u32 %0, %%cluster_ctarank;" : "=r"(rank));
    const int batch = blockIdx.x >> 3;

    const int row_local  = wid * 4 + (lane >> 3);       // 0..31
    const int row_global = (int)rank * 32 + row_local;  // 0..255
    const int colg       = lane & 7;                    // k-col group

    // A chunk in registers: A[row_global, colg*32 .. +32)
    float a[32];
    #pragma unroll
    for (int j = 0; j < 32; j++)
        a[j] = A[(size_t)row_global * 256 + colg * 32 + j];

    const float g_r = ln_g[tid];
    const float b_r = ln_b[tid];

    for (int i = tid; i < 256 + 32; i += 256) s_pad[i] = 0.f;

    const uint32_t bar0 = smem_u32(&bars[0]);
    const uint32_t bar1 = smem_u32(&bars[1]);
    if (tid == 0) {
        mbar_init(bar0, 1);
        mbar_init(bar1, 1);
        arrive_expect_tx(bar0, TX_BYTES);   // pre-arm step 0
        arrive_expect_tx(bar1, TX_BYTES);   // pre-arm step 1
    }

    // sender side: threads 0..6 each own one peer CTA
    const uint32_t src_stage0 = smem_u32(&stage[0][0]);
    const uint32_t src_stage1 = smem_u32(&stage[1][0]);
    uint32_t dst_raw0 = 0, dst_raw1 = 0, dst_bar0 = 0, dst_bar1 = 0;
    if (tid < 7) {
        uint32_t dest = (uint32_t)tid + ((uint32_t)tid >= rank ? 1u : 0u);
        // peer's raw[p] slot for MY rows (same smem offset, mapped to dest CTA)
        dst_raw0 = mapa_u32(smem_u32(&raw[0][rank * 32]), dest);
        dst_raw1 = mapa_u32(smem_u32(&raw[1][rank * 32]), dest);
        dst_bar0 = mapa_u32(bar0, dest);
        dst_bar1 = mapa_u32(bar1, dest);
    }
    __syncthreads();
    cluster_sync_();   // all barriers armed cluster-wide before any traffic

    const float* bu_base = g_Bu + (size_t)batch * SS * NN + row_global;
    float* st_base = states + (size_t)batch * SS * NN;
    float bu_cur = __ldg(bu_base);   // t = 0

    for (int t = 0; t < SS; t++) {
        const int p = t & 1;

        // prefetch next step's Bu (hidden behind this step's latency)
        float bu_nxt = 0.f;
        if (t + 1 < SS) bu_nxt = __ldg(bu_base + (size_t)(t + 1) * NN);

        // register GEMV: partial over k in [colg*32, +32)
        const float4* sv = (const float4*)&s_pad[colg * 36];
        float acc0 = 0.f, acc1 = 0.f, acc2 = 0.f, acc3 = 0.f;
        #pragma unroll
        for (int j = 0; j < 8; j++) {
            float4 v = sv[j];
            acc0 += a[4 * j + 0] * v.x;
            acc1 += a[4 * j + 1] * v.y;
            acc2 += a[4 * j + 2] * v.z;
            acc3 += a[4 * j + 3] * v.w;
        }
        float dot = (acc0 + acc1) + (acc2 + acc3);
        dot += __shfl_xor_sync(0xffffffffu, dot, 1);
        dot += __shfl_xor_sync(0xffffffffu, dot, 2);
        dot += __shfl_xor_sync(0xffffffffu, dot, 4);
        const float val = dot + bu_cur;

        // stage outgoing 32 values; self-slice written directly (no transit)
        if (colg == 0) {
            stage[p][row_local] = val;
            raw[p][(int)rank * 32 + row_local] = val;
        }
        __syncthreads();

        // 7 bulk copies, one per peer; data + tx land on peer's barrier
        if (tid < 7) {
            fence_proxy_async_cta();
            bulk_copy_cluster(p ? dst_raw1 : dst_raw0,
                              p ? src_stage1 : src_stage0,
                              128u,
                              p ? dst_bar1 : dst_bar0);
        }

        // warp 0 alone waits (CTA-scope acquire); thread 0 re-arms for t+2
        if (wid == 0) {
            wait_parity_cta(p ? bar1 : bar0, (uint32_t)((t >> 1) & 1));
            if (lane == 0) arrive_expect_tx(p ? bar1 : bar0, TX_BYTES);
        }
        __syncthreads();

        // redundant per-warp LN stats over all 256 values
        const float* rb = raw[p];
        const float4* r4 = (const float4*)rb;
        float sum = 0.f, sq = 0.f;
        #pragma unroll
        for (int q = 0; q < 2; q++) {
            float4 v = r4[lane * 2 + q];
            sum += v.x + v.y + v.z + v.w;
            sq  += v.x * v.x + v.y * v.y + v.z * v.z + v.w * v.w;
        }
        #pragma unroll
        for (int o = 16; o >= 1; o >>= 1) {
            sum += __shfl_xor_sync(0xffffffffu, sum, o);
            sq  += __shfl_xor_sync(0xffffffffu, sq,  o);
        }
        const float mu  = sum * (1.f / 256.f);
        const float var = sq * (1.f / 256.f) - mu * mu;
        const float rs  = rsqrtf(var + 1e-5f);

        const float v = rb[tid];
        float y = (v - mu) * rs * g_r + b_r;
        y = fmaxf(y, 0.f);
        s_pad[SPAD(tid)] = y;
        if ((tid >> 5) == (int)rank)                      // own 32-row chunk
            st_base[(size_t)t * NN + tid] = y;

        bu_cur = bu_nxt;
        __syncthreads();   // s_pad / stage ready for next iteration
    }
    cluster_sync_();
}

// ---------------------------------------------------------------------------
// launch
// ---------------------------------------------------------------------------
extern "C" void kernel_launch(void* const* d_in, const int* in_sizes, int n_in,
                              void* d_out, int out_size)
{
    const float* u    = (const float*)d_in[0];
    const float* A    = (const float*)d_in[1];
    const float* B_w  = (const float*)d_in[2];
    const float* B_b  = (const float*)d_in[3];
    const float* ln_g = (const float*)d_in[4];
    const float* ln_b = (const float*)d_in[5];
    const float* C_w  = (const float*)d_in[6];
    const float* C_b  = (const float*)d_in[7];

    float* out     = (float*)d_out;
    float* states  = out;
    float* outputs = out + STATES_ELEMS;

    float* bu_ptr = nullptr;
    cudaGetSymbolAddress((void**)&bu_ptr, g_Bu);

    dim3 ggrid(512, 2);
    // Bu = u @ B_w^T + B_b
    gemm_nt_kernel<<<ggrid, 256>>>(u, B_w, B_b, bu_ptr);
    // sequential scan (16 clusters x 8 CTAs)
    scan_kernel<<<128, 256>>>(A, ln_g, ln_b, states);
    // outputs = states @ C_w^T + C_b
    gemm_nt_kernel<<<ggrid, 256>>>(states, C_w, C_b, outputs);
}

// round 8
// speedup vs baseline: 1.1763x; 1.1763x over previous
#include <cuda_runtime.h>
#include <cuda_bf16.h>
#include <cstdint>

// ---------------------------------------------------------------------------
// Problem: B=16, S=4096, IN=N=OUT=256
//   Bu = u @ B_w^T + B_b                      (GEMM 65536x256x256)
//   s_t = relu(LN(s_{t-1} @ A^T + Bu_t))      (sequential scan, 16 lanes)
//   out = states @ C_w^T + C_b                (GEMM 65536x256x256)
// d_out = [states (16*4096*256) | outputs (16*4096*256)] fp32
// ---------------------------------------------------------------------------

#define BB 16
#define SS 4096
#define NN 256
static const size_t STATES_ELEMS = (size_t)BB * SS * NN;

// scratch for Bu (64 MB) — static device array (no allocation)
__device__ float g_Bu[(size_t)BB * SS * NN];

// ---------------------------------------------------------------------------
// helpers
// ---------------------------------------------------------------------------
__device__ __forceinline__ uint32_t smem_u32(const void* p) {
    uint32_t a;
    asm("{ .reg .u64 t; cvta.to.shared.u64 t, %1; cvt.u32.u64 %0, t; }"
        : "=r"(a) : "l"(p));
    return a;
}
__device__ __forceinline__ uint32_t mapa_u32(uint32_t a, uint32_t rank) {
    uint32_t r;
    asm("mapa.shared::cluster.u32 %0, %1, %2;" : "=r"(r) : "r"(a), "r"(rank));
    return r;
}
__device__ __forceinline__ void mbar_init(uint32_t mbar, uint32_t count) {
    asm volatile("mbarrier.init.shared.b64 [%0], %1;" :: "r"(mbar), "r"(count) : "memory");
}
__device__ __forceinline__ void arrive_expect_tx(uint32_t mbar, uint32_t tx) {
    asm volatile("mbarrier.arrive.expect_tx.shared.b64 _, [%0], %1;"
                 :: "r"(mbar), "r"(tx) : "memory");
}
// vectorized async store to a remote CTA's smem; 16 B of data + tx land on the
// remote mbarrier in one message (async proxy, no producer-side fence)
__device__ __forceinline__ void st_async_v4(uint32_t dst_cluster,
                                            float x, float y, float z, float w,
                                            uint32_t remote_mbar) {
    asm volatile("st.async.shared::cluster.mbarrier::complete_tx::bytes.v4.b32 "
                 "[%0], {%1, %2, %3, %4}, [%5];"
                 :: "r"(dst_cluster),
                    "r"(__float_as_uint(x)), "r"(__float_as_uint(y)),
                    "r"(__float_as_uint(z)), "r"(__float_as_uint(w)),
                    "r"(remote_mbar)
                 : "memory");
}
__device__ __forceinline__ void wait_parity_cluster(uint32_t mbar, uint32_t ph) {
    asm volatile(
        "{\n\t"
        ".reg .pred P;\n\t"
        "WL_%=:\n\t"
        "mbarrier.try_wait.parity.acquire.cluster.shared::cta.b64 P, [%0], %1, 0x989680;\n\t"
        "@P bra.uni WD_%=;\n\t"
        "bra.uni WL_%=;\n\t"
        "WD_%=:\n\t"
        "}"
        :: "r"(mbar), "r"(ph) : "memory");
}
__device__ __forceinline__ void cluster_sync_() {
    asm volatile("barrier.cluster.arrive.aligned;" ::: "memory");
    asm volatile("barrier.cluster.wait.aligned;" ::: "memory");
}

// ---------------------------------------------------------------------------
// GEMM (NT):  C[m,n] = sum_k A[m,k] * W[n,k] + bias[n]
// M = 65536, N = 256, K = 256.  Tile 128x128, BK=8, 256 thr, 8x8 per thread.
// (measured 220us, regs=111)
// ---------------------------------------------------------------------------
__global__ __launch_bounds__(256)
void gemm_nt_kernel(const float* __restrict__ Amat,
                    const float* __restrict__ Wmat,
                    const float* __restrict__ bias,
                    float* __restrict__ C)
{
    __shared__ float As[8][128];
    __shared__ float Ws[8][128];

    const int tid = threadIdx.x;
    const int bm = blockIdx.x;
    const int bn = blockIdx.y;

    const int lrow = tid >> 1;          // 0..127
    const int kq   = (tid & 1) * 4;     // 0 or 4

    const float* ga = Amat + ((size_t)(bm * 128 + lrow)) * 256 + kq;
    const float* gw = Wmat + ((size_t)(bn * 128 + lrow)) * 256 + kq;

    const int ty = tid >> 4;            // 0..15 -> rows ty*8..+8
    const int tx = tid & 15;            // 0..15 -> cols tx*8..+8

    float acc[8][8];
    #pragma unroll
    for (int i = 0; i < 8; i++)
        #pragma unroll
        for (int j = 0; j < 8; j++) acc[i][j] = 0.f;

    for (int kt = 0; kt < 256; kt += 8) {
        float4 va = *(const float4*)(ga + kt);
        float4 vw = *(const float4*)(gw + kt);
        __syncthreads();
        As[kq + 0][lrow] = va.x; As[kq + 1][lrow] = va.y;
        As[kq + 2][lrow] = va.z; As[kq + 3][lrow] = va.w;
        Ws[kq + 0][lrow] = vw.x; Ws[kq + 1][lrow] = vw.y;
        Ws[kq + 2][lrow] = vw.z; Ws[kq + 3][lrow] = vw.w;
        __syncthreads();

        #pragma unroll
        for (int k = 0; k < 8; k++) {
            float4 a0 = *(const float4*)&As[k][ty * 8];
            float4 a1 = *(const float4*)&As[k][ty * 8 + 4];
            float4 b0 = *(const float4*)&Ws[k][tx * 8];
            float4 b1 = *(const float4*)&Ws[k][tx * 8 + 4];
            float ar[8] = {a0.x, a0.y, a0.z, a0.w, a1.x, a1.y, a1.z, a1.w};
            float br[8] = {b0.x, b0.y, b0.z, b0.w, b1.x, b1.y, b1.z, b1.w};
            #pragma unroll
            for (int i = 0; i < 8; i++)
                #pragma unroll
                for (int j = 0; j < 8; j++)
                    acc[i][j] += ar[i] * br[j];
        }
    }

    float bs[8];
    #pragma unroll
    for (int j = 0; j < 8; j++) bs[j] = bias[bn * 128 + tx * 8 + j];

    #pragma unroll
    for (int i = 0; i < 8; i++) {
        size_t m = (size_t)bm * 128 + ty * 8 + i;
        float4 o0, o1;
        o0.x = acc[i][0] + bs[0]; o0.y = acc[i][1] + bs[1];
        o0.z = acc[i][2] + bs[2]; o0.w = acc[i][3] + bs[3];
        o1.x = acc[i][4] + bs[4]; o1.y = acc[i][5] + bs[5];
        o1.z = acc[i][6] + bs[6]; o1.w = acc[i][7] + bs[7];
        float* cp = C + m * 256 + bn * 128 + tx * 8;
        *(float4*)(cp)     = o0;
        *(float4*)(cp + 4) = o1;
    }
}

// ---------------------------------------------------------------------------
// Scan kernel: 16 clusters of 8 CTAs (one cluster per batch lane).
// CTA rank r holds A rows [32r, 32r+32) in REGISTERS (32 regs/thread).
// Per step:
//   register GEMV -> 8-lane shfl reduce (every lane holds its row's value)
//   -> 4x shfl.idx gathers the warp's 4 row values into lanes 0..7, which each
//      fire ONE st.async.v4.b32 (16 B) at destination CTA = lane, completing
//      on the dest's tx-counting mbarrier (8 src CTAs x 8 warps x 16 B =
//      1024 B = 64 messages per barrier per step, vs 256 in round 5)
//   -> warp 0 alone waits the parity barrier, thread 0 re-arms for t+2,
//      __syncthreads releases the CTA
//   -> redundant per-warp LN stats + normalize + relu -> next step.
// ---------------------------------------------------------------------------
#define SPAD(i) ((i) + ((i) >> 5) * 4)   // pad 16B per 32 floats
#define TX_BYTES 1024u                   // 64 msgs * 16 B per phase

__global__ __launch_bounds__(256)
__cluster_dims__(8, 1, 1)
void scan_kernel(const float* __restrict__ A,
                 const float* __restrict__ ln_g,
                 const float* __restrict__ ln_b,
                 float* __restrict__ states)
{
    __shared__ __align__(16) float s_pad[256 + 32];
    __shared__ __align__(16) float raw[2][256];     // incoming, by step parity
    __shared__ __align__(8)  unsigned long long bars[2];

    const int tid  = threadIdx.x;
    const int lane = tid & 31;
    const int wid  = tid >> 5;

    uint32_t rank;
    asm("mov.u32 %0, %%cluster_ctarank;" : "=r"(rank));
    const int batch = blockIdx.x >> 3;

    const int row_local  = wid * 4 + (lane >> 3);       // 0..31
    const int row_global = (int)rank * 32 + row_local;  // 0..255
    const int colg       = lane & 7;                    // k-col group

    // A chunk in registers: A[row_global, colg*32 .. +32)
    float a[32];
    #pragma unroll
    for (int j = 0; j < 32; j++)
        a[j] = A[(size_t)row_global * 256 + colg * 32 + j];

    const float g_r = ln_g[tid];
    const float b_r = ln_b[tid];

    for (int i = tid; i < 256 + 32; i += 256) s_pad[i] = 0.f;

    const uint32_t bar0 = smem_u32(&bars[0]);
    const uint32_t bar1 = smem_u32(&bars[1]);
    if (tid == 0) {
        mbar_init(bar0, 1);
        mbar_init(bar1, 1);
        arrive_expect_tx(bar0, TX_BYTES);   // pre-arm step 0
        arrive_expect_tx(bar1, TX_BYTES);   // pre-arm step 1
    }

    // sender side: lanes 0..7 of each warp send this warp's 4 rows (16 B) to
    // dest CTA = lane; remote slot = raw[p][rank*32 + wid*4] on that CTA
    const uint32_t dst_raw0 = mapa_u32(smem_u32(&raw[0][rank * 32 + wid * 4]),
                                       (uint32_t)colg);
    const uint32_t dst_raw1 = mapa_u32(smem_u32(&raw[1][rank * 32 + wid * 4]),
                                       (uint32_t)colg);
    const uint32_t dst_bar0 = mapa_u32(bar0, (uint32_t)colg);
    const uint32_t dst_bar1 = mapa_u32(bar1, (uint32_t)colg);

    __syncthreads();
    cluster_sync_();   // all barriers armed cluster-wide before any traffic

    const float* bu_base = g_Bu + (size_t)batch * SS * NN + row_global;
    float* st_base = states + (size_t)batch * SS * NN;
    float bu_cur = __ldg(bu_base);   // t = 0

    for (int t = 0; t < SS; t++) {
        const int p = t & 1;

        // prefetch next step's Bu (hidden behind this step's latency)
        float bu_nxt = 0.f;
        if (t + 1 < SS) bu_nxt = __ldg(bu_base + (size_t)(t + 1) * NN);

        // register GEMV: partial over k in [colg*32, +32)
        const float4* sv = (const float4*)&s_pad[colg * 36];
        float acc0 = 0.f, acc1 = 0.f, acc2 = 0.f, acc3 = 0.f;
        #pragma unroll
        for (int j = 0; j < 8; j++) {
            float4 v = sv[j];
            acc0 += a[4 * j + 0] * v.x;
            acc1 += a[4 * j + 1] * v.y;
            acc2 += a[4 * j + 2] * v.z;
            acc3 += a[4 * j + 3] * v.w;
        }
        float dot = (acc0 + acc1) + (acc2 + acc3);
        dot += __shfl_xor_sync(0xffffffffu, dot, 1);
        dot += __shfl_xor_sync(0xffffffffu, dot, 2);
        dot += __shfl_xor_sync(0xffffffffu, dot, 4);
        const float val = dot + bu_cur;   // this row's raw value (all 8 lanes)

        // gather the warp's 4 row values into every lane (uniform idx per lane)
        const int base = lane & 7;
        const float r0 = __shfl_sync(0xffffffffu, val, base);
        const float r1 = __shfl_sync(0xffffffffu, val, base + 8);
        const float r2 = __shfl_sync(0xffffffffu, val, base + 16);
        const float r3 = __shfl_sync(0xffffffffu, val, base + 24);

        // lanes 0..7: one 16-byte async message to dest CTA = lane
        if (lane < 8) {
            st_async_v4(p ? dst_raw1 : dst_raw0, r0, r1, r2, r3,
                        p ? dst_bar1 : dst_bar0);
        }

        // warp 0 alone waits; thread 0 re-arms for t+2; bar releases the CTA
        if (wid == 0) {
            wait_parity_cluster(p ? bar1 : bar0, (uint32_t)((t >> 1) & 1));
            if (lane == 0) arrive_expect_tx(p ? bar1 : bar0, TX_BYTES);
        }
        __syncthreads();

        // redundant per-warp LN stats over all 256 values
        const float* rb = raw[p];
        const float4* r4 = (const float4*)rb;
        float sum = 0.f, sq = 0.f;
        #pragma unroll
        for (int q = 0; q < 2; q++) {
            float4 v = r4[lane * 2 + q];
            sum += v.x + v.y + v.z + v.w;
            sq  += v.x * v.x + v.y * v.y + v.z * v.z + v.w * v.w;
        }
        #pragma unroll
        for (int o = 16; o >= 1; o >>= 1) {
            sum += __shfl_xor_sync(0xffffffffu, sum, o);
            sq  += __shfl_xor_sync(0xffffffffu, sq,  o);
        }
        const float mu  = sum * (1.f / 256.f);
        const float var = sq * (1.f / 256.f) - mu * mu;
        const float rs  = rsqrtf(var + 1e-5f);

        const float v = rb[tid];
        float y = (v - mu) * rs * g_r + b_r;
        y = fmaxf(y, 0.f);
        s_pad[SPAD(tid)] = y;
        if ((tid >> 5) == (int)rank)                      // own 32-row chunk
            st_base[(size_t)t * NN + tid] = y;

        bu_cur = bu_nxt;
        __syncthreads();   // s_pad ready for next iteration
    }
    cluster_sync_();
}

// ---------------------------------------------------------------------------
// launch
// ---------------------------------------------------------------------------
extern "C" void kernel_launch(void* const* d_in, const int* in_sizes, int n_in,
                              void* d_out, int out_size)
{
    const float* u    = (const float*)d_in[0];
    const float* A    = (const float*)d_in[1];
    const float* B_w  = (const float*)d_in[2];
    const float* B_b  = (const float*)d_in[3];
    const float* ln_g = (const float*)d_in[4];
    const float* ln_b = (const float*)d_in[5];
    const float* C_w  = (const float*)d_in[6];
    const float* C_b  = (const float*)d_in[7];

    float* out     = (float*)d_out;
    float* states  = out;
    float* outputs = out + STATES_ELEMS;

    float* bu_ptr = nullptr;
    cudaGetSymbolAddress((void**)&bu_ptr, g_Bu);

    dim3 ggrid(512, 2);
    // Bu = u @ B_w^T + B_b
    gemm_nt_kernel<<<ggrid, 256>>>(u, B_w, B_b, bu_ptr);
    // sequential scan (16 clusters x 8 CTAs)
    scan_kernel<<<128, 256>>>(A, ln_g, ln_b, states);
    // outputs = states @ C_w^T + C_b
    gemm_nt_kernel<<<ggrid, 256>>>(states, C_w, C_b, outputs);
}

// round 9
// speedup vs baseline: 1.2048x; 1.0242x over previous
#include <cuda_runtime.h>
#include <cuda_bf16.h>
#include <cstdint>

// ---------------------------------------------------------------------------
// Problem: B=16, S=4096, IN=N=OUT=256
//   Bu = u @ B_w^T + B_b                      (GEMM 65536x256x256)
//   s_t = relu(LN(s_{t-1} @ A^T + Bu_t))      (sequential scan, 16 lanes)
//   out = states @ C_w^T + C_b                (GEMM 65536x256x256)
// d_out = [states (16*4096*256) | outputs (16*4096*256)] fp32
// ---------------------------------------------------------------------------

#define BB 16
#define SS 4096
#define NN 256
static const size_t STATES_ELEMS = (size_t)BB * SS * NN;

// scratch for Bu (64 MB) — static device array (no allocation)
__device__ float g_Bu[(size_t)BB * SS * NN];

// ---------------------------------------------------------------------------
// helpers
// ---------------------------------------------------------------------------
__device__ __forceinline__ uint32_t smem_u32(const void* p) {
    uint32_t a;
    asm("{ .reg .u64 t; cvta.to.shared.u64 t, %1; cvt.u32.u64 %0, t; }"
        : "=r"(a) : "l"(p));
    return a;
}
__device__ __forceinline__ uint32_t mapa_u32(uint32_t a, uint32_t rank) {
    uint32_t r;
    asm("mapa.shared::cluster.u32 %0, %1, %2;" : "=r"(r) : "r"(a), "r"(rank));
    return r;
}
__device__ __forceinline__ void mbar_init(uint32_t mbar, uint32_t count) {
    asm volatile("mbarrier.init.shared.b64 [%0], %1;" :: "r"(mbar), "r"(count) : "memory");
}
__device__ __forceinline__ void arrive_expect_tx(uint32_t mbar, uint32_t tx) {
    asm volatile("mbarrier.arrive.expect_tx.shared.b64 _, [%0], %1;"
                 :: "r"(mbar), "r"(tx) : "memory");
}
// per-thread async store to a remote CTA's smem; data + tx land on the remote
// mbarrier (async proxy, no producer-side fence needed)
__device__ __forceinline__ void st_async_f32(uint32_t dst_cluster, float v,
                                             uint32_t remote_mbar) {
    asm volatile("st.async.shared::cluster.mbarrier::complete_tx::bytes.b32 "
                 "[%0], %1, [%2];"
                 :: "r"(dst_cluster), "r"(__float_as_uint(v)), "r"(remote_mbar)
                 : "memory");
}
// CTA-scope acquire wait — the fast TRYWAIT path (~90cyc vs ~490 for the
// cluster-scope UCGABAR wait). complete_tx delivery already makes the
// async-proxy data CTA-visible at the barrier (standard TMA-consumer pattern).
__device__ __forceinline__ void wait_parity_cta(uint32_t mbar, uint32_t ph) {
    asm volatile(
        "{\n\t"
        ".reg .pred P;\n\t"
        "WL_%=:\n\t"
        "mbarrier.try_wait.parity.acquire.cta.shared::cta.b64 P, [%0], %1, 0x989680;\n\t"
        "@P bra.uni WD_%=;\n\t"
        "bra.uni WL_%=;\n\t"
        "WD_%=:\n\t"
        "}"
        :: "r"(mbar), "r"(ph) : "memory");
}
__device__ __forceinline__ void cluster_sync_() {
    asm volatile("barrier.cluster.arrive.aligned;" ::: "memory");
    asm volatile("barrier.cluster.wait.aligned;" ::: "memory");
}

// ---------------------------------------------------------------------------
// GEMM (NT):  C[m,n] = sum_k A[m,k] * W[n,k] + bias[n]
// M = 65536, N = 256, K = 256.  Tile 128x128, BK=8, 256 thr, 8x8 per thread.
// (measured 220us, regs=111)
// ---------------------------------------------------------------------------
__global__ __launch_bounds__(256)
void gemm_nt_kernel(const float* __restrict__ Amat,
                    const float* __restrict__ Wmat,
                    const float* __restrict__ bias,
                    float* __restrict__ C)
{
    __shared__ float As[8][128];
    __shared__ float Ws[8][128];

    const int tid = threadIdx.x;
    const int bm = blockIdx.x;
    const int bn = blockIdx.y;

    const int lrow = tid >> 1;          // 0..127
    const int kq   = (tid & 1) * 4;     // 0 or 4

    const float* ga = Amat + ((size_t)(bm * 128 + lrow)) * 256 + kq;
    const float* gw = Wmat + ((size_t)(bn * 128 + lrow)) * 256 + kq;

    const int ty = tid >> 4;            // 0..15 -> rows ty*8..+8
    const int tx = tid & 15;            // 0..15 -> cols tx*8..+8

    float acc[8][8];
    #pragma unroll
    for (int i = 0; i < 8; i++)
        #pragma unroll
        for (int j = 0; j < 8; j++) acc[i][j] = 0.f;

    for (int kt = 0; kt < 256; kt += 8) {
        float4 va = *(const float4*)(ga + kt);
        float4 vw = *(const float4*)(gw + kt);
        __syncthreads();
        As[kq + 0][lrow] = va.x; As[kq + 1][lrow] = va.y;
        As[kq + 2][lrow] = va.z; As[kq + 3][lrow] = va.w;
        Ws[kq + 0][lrow] = vw.x; Ws[kq + 1][lrow] = vw.y;
        Ws[kq + 2][lrow] = vw.z; Ws[kq + 3][lrow] = vw.w;
        __syncthreads();

        #pragma unroll
        for (int k = 0; k < 8; k++) {
            float4 a0 = *(const float4*)&As[k][ty * 8];
            float4 a1 = *(const float4*)&As[k][ty * 8 + 4];
            float4 b0 = *(const float4*)&Ws[k][tx * 8];
            float4 b1 = *(const float4*)&Ws[k][tx * 8 + 4];
            float ar[8] = {a0.x, a0.y, a0.z, a0.w, a1.x, a1.y, a1.z, a1.w};
            float br[8] = {b0.x, b0.y, b0.z, b0.w, b1.x, b1.y, b1.z, b1.w};
            #pragma unroll
            for (int i = 0; i < 8; i++)
                #pragma unroll
                for (int j = 0; j < 8; j++)
                    acc[i][j] += ar[i] * br[j];
        }
    }

    float bs[8];
    #pragma unroll
    for (int j = 0; j < 8; j++) bs[j] = bias[bn * 128 + tx * 8 + j];

    #pragma unroll
    for (int i = 0; i < 8; i++) {
        size_t m = (size_t)bm * 128 + ty * 8 + i;
        float4 o0, o1;
        o0.x = acc[i][0] + bs[0]; o0.y = acc[i][1] + bs[1];
        o0.z = acc[i][2] + bs[2]; o0.w = acc[i][3] + bs[3];
        o1.x = acc[i][4] + bs[4]; o1.y = acc[i][5] + bs[5];
        o1.z = acc[i][6] + bs[6]; o1.w = acc[i][7] + bs[7];
        float* cp = C + m * 256 + bn * 128 + tx * 8;
        *(float4*)(cp)     = o0;
        *(float4*)(cp + 4) = o1;
    }
}

// ---------------------------------------------------------------------------
// Scan kernel: 16 clusters of 8 CTAs (one cluster per batch lane).
// CTA rank r holds A rows [32r, 32r+32) in REGISTERS (32 regs/thread).
// Per step:
//   register GEMV -> 8-lane shfl reduce (every lane holds its row's value)
//   -> every thread st.async's its row value to dest CTA (colg), completing
//      on the dest's tx-counting mbarrier (expect 256*4B per phase)
//   -> warp 0 alone waits the parity barrier with CTA-SCOPE acquire (fast
//      TRYWAIT path; async-proxy delivery is already CTA-visible), thread 0
//      re-arms for t+2, __syncthreads releases the CTA
//   -> redundant per-warp LN stats + normalize + relu -> next step.
// ---------------------------------------------------------------------------
#define SPAD(i) ((i) + ((i) >> 5) * 4)   // pad 16B per 32 floats
#define TX_BYTES 1024u                   // 256 stores * 4 B per phase

__global__ __launch_bounds__(256)
__cluster_dims__(8, 1, 1)
void scan_kernel(const float* __restrict__ A,
                 const float* __restrict__ ln_g,
                 const float* __restrict__ ln_b,
                 float* __restrict__ states)
{
    __shared__ __align__(16) float s_pad[256 + 32];
    __shared__ __align__(16) float raw[2][256];     // incoming, by step parity
    __shared__ __align__(8)  unsigned long long bars[2];

    const int tid  = threadIdx.x;
    const int lane = tid & 31;
    const int wid  = tid >> 5;

    uint32_t rank;
    asm("mov.u32 %0, %%cluster_ctarank;" : "=r"(rank));
    const int batch = blockIdx.x >> 3;

    const int row_local  = wid * 4 + (lane >> 3);       // 0..31
    const int row_global = (int)rank * 32 + row_local;  // 0..255
    const int colg       = lane & 7;                    // k-col group == dest CTA

    // A chunk in registers: A[row_global, colg*32 .. +32)
    float a[32];
    #pragma unroll
    for (int j = 0; j < 32; j++)
        a[j] = A[(size_t)row_global * 256 + colg * 32 + j];

    const float g_r = ln_g[tid];
    const float b_r = ln_b[tid];

    for (int i = tid; i < 256 + 32; i += 256) s_pad[i] = 0.f;

    const uint32_t bar0 = smem_u32(&bars[0]);
    const uint32_t bar1 = smem_u32(&bars[1]);
    if (tid == 0) {
        mbar_init(bar0, 1);
        mbar_init(bar1, 1);
        arrive_expect_tx(bar0, TX_BYTES);   // pre-arm step 0
        arrive_expect_tx(bar1, TX_BYTES);   // pre-arm step 1
    }

    // remote addresses for this thread's row value (both parities)
    const uint32_t dst_raw0 = mapa_u32(smem_u32(&raw[0][row_global]), (uint32_t)colg);
    const uint32_t dst_raw1 = mapa_u32(smem_u32(&raw[1][row_global]), (uint32_t)colg);
    const uint32_t dst_bar0 = mapa_u32(bar0, (uint32_t)colg);
    const uint32_t dst_bar1 = mapa_u32(bar1, (uint32_t)colg);

    __syncthreads();
    cluster_sync_();   // all barriers armed cluster-wide before any traffic

    const float* bu_base = g_Bu + (size_t)batch * SS * NN + row_global;
    float* st_base = states + (size_t)batch * SS * NN;
    float bu_cur = __ldg(bu_base);   // t = 0

    for (int t = 0; t < SS; t++) {
        const int p = t & 1;

        // prefetch next step's Bu (hidden behind this step's latency)
        float bu_nxt = 0.f;
        if (t + 1 < SS) bu_nxt = __ldg(bu_base + (size_t)(t + 1) * NN);

        // register GEMV: partial over k in [colg*32, +32)
        const float4* sv = (const float4*)&s_pad[colg * 36];
        float acc0 = 0.f, acc1 = 0.f, acc2 = 0.f, acc3 = 0.f;
        #pragma unroll
        for (int j = 0; j < 8; j++) {
            float4 v = sv[j];
            acc0 += a[4 * j + 0] * v.x;
            acc1 += a[4 * j + 1] * v.y;
            acc2 += a[4 * j + 2] * v.z;
            acc3 += a[4 * j + 3] * v.w;
        }
        float dot = (acc0 + acc1) + (acc2 + acc3);
        dot += __shfl_xor_sync(0xffffffffu, dot, 1);
        dot += __shfl_xor_sync(0xffffffffu, dot, 2);
        dot += __shfl_xor_sync(0xffffffffu, dot, 4);
        const float val = dot + bu_cur;

        // fire this row's value at dest CTA (data + tx in one async store)
        st_async_f32(p ? dst_raw1 : dst_raw0, val, p ? dst_bar1 : dst_bar0);

        // warp 0 alone waits (cta-scope acquire); thread 0 re-arms for t+2
        if (wid == 0) {
            wait_parity_cta(p ? bar1 : bar0, (uint32_t)((t >> 1) & 1));
            if (lane == 0) arrive_expect_tx(p ? bar1 : bar0, TX_BYTES);
        }
        __syncthreads();

        // redundant per-warp LN stats over all 256 values
        const float* rb = raw[p];
        const float4* r4 = (const float4*)rb;
        float sum = 0.f, sq = 0.f;
        #pragma unroll
        for (int q = 0; q < 2; q++) {
            float4 v = r4[lane * 2 + q];
            sum += v.x + v.y + v.z + v.w;
            sq  += v.x * v.x + v.y * v.y + v.z * v.z + v.w * v.w;
        }
        #pragma unroll
        for (int o = 16; o >= 1; o >>= 1) {
            sum += __shfl_xor_sync(0xffffffffu, sum, o);
            sq  += __shfl_xor_sync(0xffffffffu, sq,  o);
        }
        const float mu  = sum * (1.f / 256.f);
        const float var = sq * (1.f / 256.f) - mu * mu;
        const float rs  = rsqrtf(var + 1e-5f);

        const float v = rb[tid];
        float y = (v - mu) * rs * g_r + b_r;
        y = fmaxf(y, 0.f);
        s_pad[SPAD(tid)] = y;
        if ((tid >> 5) == (int)rank)                      // own 32-row chunk
            st_base[(size_t)t * NN + tid] = y;

        bu_cur = bu_nxt;
        __syncthreads();   // s_pad ready for next iteration
    }
    cluster_sync_();
}

// ---------------------------------------------------------------------------
// launch
// ---------------------------------------------------------------------------
extern "C" void kernel_launch(void* const* d_in, const int* in_sizes, int n_in,
                              void* d_out, int out_size)
{
    const float* u    = (const float*)d_in[0];
    const float* A    = (const float*)d_in[1];
    const float* B_w  = (const float*)d_in[2];
    const float* B_b  = (const float*)d_in[3];
    const float* ln_g = (const float*)d_in[4];
    const float* ln_b = (const float*)d_in[5];
    const float* C_w  = (const float*)d_in[6];
    const float* C_b  = (const float*)d_in[7];

    float* out     = (float*)d_out;
    float* states  = out;
    float* outputs = out + STATES_ELEMS;

    float* bu_ptr = nullptr;
    cudaGetSymbolAddress((void**)&bu_ptr, g_Bu);

    dim3 ggrid(512, 2);
    // Bu = u @ B_w^T + B_b
    gemm_nt_kernel<<<ggrid, 256>>>(u, B_w, B_b, bu_ptr);
    // sequential scan (16 clusters x 8 CTAs)
    scan_kernel<<<128, 256>>>(A, ln_g, ln_b, states);
    // outputs = states @ C_w^T + C_b
    gemm_nt_kernel<<<ggrid, 256>>>(states, C_w, C_b, outputs);
}